// round 12
// baseline (speedup 1.0000x reference)
#include <cuda_runtime.h>
#include <cuda_fp16.h>
#include <stdint.h>
#include <math.h>

// ---------------------------------------------------------------------------
// MomentumAttention (linear attention), fp16 2-term MMA (A single, B hi/lo):
//   Qf = (elu(Q)+1)*scale ; Kf = (elu(K)+1)*mask*scale*mw[l] ; Vf = V*mask
//   KV[d][e] = sum_l Kf[l][d]*Vf[l][e] ;  X = Qf @ KV
// Legacy mma.sync path (tcgen05 unavailable on this build target).
// ---------------------------------------------------------------------------

#define LLc 8192
#define DDc 128
#define BHc 32
#define CHUNKSc 16
#define CLc (LLc / CHUNKSc)   // 512

__device__ float    g_KVp[CHUNKSc * BHc * DDc * DDc];  // per-chunk partials
__device__ float4   g_wm4[2 * LLc / 2];                // {w*m, m, w*m, m} per l-pair
__device__ uint32_t g_KVThi[BHc * DDc * (DDc / 2)];    // [bh][e][d-pair] fp16x2
__device__ uint32_t g_KVTlo[BHc * DDc * (DDc / 2)];

__device__ __forceinline__ float elup(float x) {
  return x > 0.0f ? x + 1.0f : __expf(x);
}

__device__ __forceinline__ uint32_t pack_h2(float a, float b) {
  __half2 h = __floats2half2_rn(a, b);
  return *reinterpret_cast<uint32_t*>(&h);
}

__device__ __forceinline__ void split_pair_h(float a, float b,
                                             uint32_t& hi, uint32_t& lo) {
  __half2 h = __floats2half2_rn(a, b);
  hi = *reinterpret_cast<uint32_t*>(&h);
  float ra = a - __half2float(h.x);
  float rb = b - __half2float(h.y);
  __half2 l2 = __floats2half2_rn(ra, rb);
  lo = *reinterpret_cast<uint32_t*>(&l2);
}

__device__ __forceinline__ void mma_f16(float* c, const uint32_t* a,
                                        const uint32_t* b) {
  asm volatile(
      "mma.sync.aligned.m16n8k16.row.col.f32.f16.f16.f32 "
      "{%0,%1,%2,%3},{%4,%5,%6,%7},{%8,%9},{%0,%1,%2,%3};\n"
      : "+f"(c[0]), "+f"(c[1]), "+f"(c[2]), "+f"(c[3])
      : "r"(a[0]), "r"(a[1]), "r"(a[2]), "r"(a[3]), "r"(b[0]), "r"(b[1]));
}

__device__ __forceinline__ void ldsm_x4(uint32_t* r, uint32_t addr) {
  asm volatile(
      "ldmatrix.sync.aligned.m8n8.x4.shared.b16 {%0,%1,%2,%3}, [%4];"
      : "=r"(r[0]), "=r"(r[1]), "=r"(r[2]), "=r"(r[3])
      : "r"(addr));
}

// ---------------------------------------------------------------------------
__global__ void ma_init(const float* __restrict__ mask, float scale) {
  int idx = blockIdx.x * blockDim.x + threadIdx.x;   // 0 .. 8191
  if (idx < 2 * (LLc / 2)) {
    int b = idx >> 12;
    int l = (idx & 4095) * 2;
    float m0 = mask[b * LLc + l];
    float m1 = mask[b * LLc + l + 1];
    float p0 = powf(0.9f, (float)(LLc - l));
    float p1 = powf(0.9f, (float)(LLc - l - 1));
    float w0 = scale * (1.0f - p0) * 10.0f;
    float w1 = scale * (1.0f - p1) * 10.0f;
    g_wm4[idx] = make_float4(w0 * m0, m0, w1 * m1, m1);
  }
}

// ---------------------------------------------------------------------------
// Pass 1 (unchanged from R11): A = Kf single fp16, B = Vf fp16 hi/lo.
// ---------------------------------------------------------------------------
__global__ void __launch_bounds__(256, 2)
ma_pass1(const float* __restrict__ Kin, const float* __restrict__ Vin) {
  extern __shared__ uint32_t sm[];
  const int tid = threadIdx.x;
  const int bh = blockIdx.y;
  const int b = bh >> 4;
  const int chunk = blockIdx.x;
  const float* Kg = Kin + (size_t)bh * LLc * DDc;
  const float* Vg = Vin + (size_t)bh * LLc * DDc;
  const float4* Wg = g_wm4 + (size_t)b * (LLc / 2);

  const int warp = tid >> 5, lane = tid & 31;
  const int g = lane >> 2, t = lane & 3;
  const int q = lane >> 3, r8 = lane & 7;
  const int qh = q >> 1, ql = q & 1;
  const int mo = (warp & 3) * 32;    // d
  const int no = (warp >> 2) * 64;   // e

  uint32_t smb = (uint32_t)__cvta_generic_to_shared(sm);

  uint32_t aAddr[2];
#pragma unroll
  for (int mt = 0; mt < 2; ++mt) {
    int row = mo + mt * 16 + ql * 8 + r8;
    aAddr[mt] = smb + (uint32_t)(row * 32) +
                (uint32_t)(((qh ^ ((row >> 2) & 1))) << 4);
  }
  uint32_t bAddr[4];
#pragma unroll
  for (int np = 0; np < 4; ++np) {
    int row = no + np * 16 + qh * 8 + r8;
    bAddr[np] = smb + 4096u + (uint32_t)(row * 32) +
                (uint32_t)(((ql ^ ((row >> 2) & 1))) << 4);
  }

  const int dst = tid & 127;
  const int chk = tid >> 7;
  const int schk = chk ^ ((dst >> 2) & 1);

  float C[2][8][4];
#pragma unroll
  for (int i = 0; i < 2; i++)
#pragma unroll
    for (int j = 0; j < 8; j++)
#pragma unroll
      for (int p = 0; p < 4; p++) C[i][j][p] = 0.0f;

  const int l0c = chunk * CLc;

  const int crow = tid >> 4;
  const int ccol = tid & 15;
  auto cpKV = [&](int s) {
    uint32_t kb = smb + (uint32_t)(6144 + (s % 3) * 4096) * 4u;
    uint32_t vb = kb + 8192u;
    const float* kg = Kg + (size_t)(l0c + s * 16 + crow) * DDc + ccol * 4;
    const float* vg = Vg + (size_t)(l0c + s * 16 + crow) * DDc + ccol * 4;
    uint32_t so = (uint32_t)(crow * 128 + ccol * 4) * 4u;
    asm volatile("cp.async.cg.shared.global [%0], [%1], 16;\n"
                 :: "r"(kb + so), "l"(kg));
    asm volatile("cp.async.cg.shared.global [%0], [%1], 16;\n"
                 :: "r"(kb + so + 256u), "l"(kg + 64));
    asm volatile("cp.async.cg.shared.global [%0], [%1], 16;\n"
                 :: "r"(vb + so), "l"(vg));
    asm volatile("cp.async.cg.shared.global [%0], [%1], 16;\n"
                 :: "r"(vb + so + 256u), "l"(vg + 64));
    asm volatile("cp.async.commit_group;\n" ::: "memory");
  };

  auto transform = [&](int s) {
    const uint32_t* kb = sm + 6144 + (s % 3) * 4096;
    const uint32_t* vb = kb + 2048;
    int l = l0c + s * 16 + chk * 8;
    float4 w4[4];
#pragma unroll
    for (int i = 0; i < 4; ++i) w4[i] = Wg[(l >> 1) + i];
    float kf[8], vf[8];
#pragma unroll
    for (int i = 0; i < 4; ++i) {
      int rw = (chk * 8 + 2 * i) * 128 + dst;
      float k0 = __uint_as_float(kb[rw]);
      float k1 = __uint_as_float(kb[rw + 128]);
      float v0 = __uint_as_float(vb[rw]);
      float v1 = __uint_as_float(vb[rw + 128]);
      kf[2 * i] = elup(k0) * w4[i].x;
      kf[2 * i + 1] = elup(k1) * w4[i].z;
      vf[2 * i] = v0 * w4[i].y;
      vf[2 * i + 1] = v1 * w4[i].w;
    }
    uint4 kh, vhi, vlo;
    kh.x = pack_h2(kf[0], kf[1]);
    kh.y = pack_h2(kf[2], kf[3]);
    kh.z = pack_h2(kf[4], kf[5]);
    kh.w = pack_h2(kf[6], kf[7]);
    split_pair_h(vf[0], vf[1], vhi.x, vlo.x);
    split_pair_h(vf[2], vf[3], vhi.y, vlo.y);
    split_pair_h(vf[4], vf[5], vhi.z, vlo.z);
    split_pair_h(vf[6], vf[7], vhi.w, vlo.w);
    int off = (s & 1) * 3072 + dst * 8 + (schk << 2);
    *reinterpret_cast<uint4*>(sm + off) = kh;
    *reinterpret_cast<uint4*>(sm + off + 1024) = vhi;
    *reinterpret_cast<uint4*>(sm + off + 2048) = vlo;
  };

  auto mmastep = [&](int bsel) {
    const uint32_t bb = (uint32_t)bsel * 12288u;
    uint32_t A[2][4];
#pragma unroll
    for (int mt = 0; mt < 2; ++mt) ldsm_x4(A[mt], aAddr[mt] + bb);
#pragma unroll
    for (int np = 0; np < 4; ++np) {
      uint32_t Bh[4], Bl[4];
      ldsm_x4(Bh, bAddr[np] + bb);
      ldsm_x4(Bl, bAddr[np] + bb + 4096u);
#pragma unroll
      for (int mt = 0; mt < 2; ++mt) {
        mma_f16(C[mt][2 * np], A[mt], Bh);
        mma_f16(C[mt][2 * np], A[mt], Bl);
        mma_f16(C[mt][2 * np + 1], A[mt], Bh + 2);
        mma_f16(C[mt][2 * np + 1], A[mt], Bl + 2);
      }
    }
  };

  cpKV(0);
  cpKV(1);
  cpKV(2);
  asm volatile("cp.async.wait_group 2;\n" ::: "memory");
  __syncthreads();
  transform(0);
  asm volatile("cp.async.wait_group 1;\n" ::: "memory");
  __syncthreads();

#pragma unroll 1
  for (int s = 0; s < 32; ++s) {
    if (s < 29) cpKV(s + 3);
    mmastep(s & 1);
    if (s < 31) transform(s + 1);
    if (s < 29) {
      asm volatile("cp.async.wait_group 1;\n" ::: "memory");
    } else if (s == 29) {
      asm volatile("cp.async.wait_group 0;\n" ::: "memory");
    }
    __syncthreads();
  }

  float* out = g_KVp + (size_t)(chunk * BHc + bh) * DDc * DDc;
#pragma unroll
  for (int mt = 0; mt < 2; ++mt)
#pragma unroll
    for (int nt = 0; nt < 8; ++nt) {
      int d0 = mo + mt * 16 + g;
      int e0 = no + nt * 8 + t * 2;
      *reinterpret_cast<float2*>(out + (size_t)d0 * DDc + e0) =
          make_float2(C[mt][nt][0], C[mt][nt][1]);
      *reinterpret_cast<float2*>(out + (size_t)(d0 + 8) * DDc + e0) =
          make_float2(C[mt][nt][2], C[mt][nt][3]);
    }
}

// ---------------------------------------------------------------------------
__global__ void __launch_bounds__(128) ma_reduce() {
  const int e = threadIdx.x;
  const int bh = blockIdx.x >> 6;
  const int dp = blockIdx.x & 63;
  const int d = dp * 2;
  float a0 = 0.0f, a1 = 0.0f;
  for (int c = 0; c < CHUNKSc; ++c) {
    const float* p = g_KVp + (size_t)(c * BHc + bh) * DDc * DDc;
    a0 += p[(size_t)d * DDc + e];
    a1 += p[(size_t)(d + 1) * DDc + e];
  }
  uint32_t hi, lo;
  split_pair_h(a0, a1, hi, lo);
  g_KVThi[(size_t)bh * 8192 + e * 64 + dp] = hi;
  g_KVTlo[(size_t)bh * 8192 + e * 64 + dp] = lo;
}

// ---------------------------------------------------------------------------
// Pass 2 (no e-split, mt=2): CTA = 128 l x 128 e. 8 warps as 4(l) x 2(e);
// warp tile 32 l x 64 e. B full tile smem-resident (64 KB fp16 hi/lo).
// Q per-warp cp.async ring (3 bufs x 512 words/warp), no block barriers in
// the main loop. Q read ONCE from DRAM (no e-split duplication); B LDSM per
// output halved vs e-split.
// smem words: BHI[0,8192) BLO[8192,16384) Q[16384, 16384+8*1536)
// ---------------------------------------------------------------------------
#define QOFF 16384
#define QWBUF 1536   // 3 * 512 words per warp

__global__ void __launch_bounds__(256, 2)
ma_pass2(const float* __restrict__ Qin, float* __restrict__ Xout, float scale) {
  extern __shared__ uint32_t sm[];

  const int tid = threadIdx.x;
  const int bh = blockIdx.y;
  const int l0 = blockIdx.x * 128;
  const float* Qg = Qin + (size_t)bh * LLc * DDc;
  float* Xg = Xout + (size_t)bh * LLc * DDc;

  const int warp = tid >> 5, lane = tid & 31;
  const int g = lane >> 2, t = lane & 3;
  const int q = lane >> 3, r8 = lane & 7;
  const int qh = q >> 1, ql = q & 1;
  const int lw = (warp & 3) * 32;           // warp's l offset
  const int eo = (warp >> 2) * 64;          // warp's e offset

  uint32_t smb = (uint32_t)__cvta_generic_to_shared(sm);

  // ---- stage full B once (swizzled): 128 rows x 16 uint4 ----
  {
    const uint4* shi = reinterpret_cast<const uint4*>(g_KVThi + (size_t)bh * 8192);
    const uint4* slo = reinterpret_cast<const uint4*>(g_KVTlo + (size_t)bh * 8192);
#pragma unroll
    for (int i = 0; i < 8; ++i) {
      int idx4 = tid + i * 256;        // 0..2047
      int e = idx4 >> 4, c = idx4 & 15;
      int w = e * 64 + ((c ^ (e & 7)) << 2);
      *reinterpret_cast<uint4*>(sm + w) = shi[idx4];
      *reinterpret_cast<uint4*>(sm + 8192 + w) = slo[idx4];
    }
  }

  uint32_t bBhi[4], bBlo[4];
#pragma unroll
  for (int np = 0; np < 4; ++np) {
    int row = eo + np * 16 + qh * 8 + r8;
    bBhi[np] = smb + (uint32_t)(row * 64) * 4u;
    bBlo[np] = smb + (8192u + (uint32_t)(row * 64)) * 4u;
  }

  // ---- per-warp Q ring (32 rows x 16 words per buffer) ----
  const int qrow = lane & 15;           // staging rows qrow and qrow+16
  const int qc0 = (lane >> 4) * 2;      // chunks {0,1} or {2,3}
  const uint32_t qbase = smb + (uint32_t)(QOFF + warp * QWBUF) * 4u;

  auto cpQ = [&](int kk) {
    uint32_t sb = qbase + (uint32_t)((kk % 3) * 512) * 4u;
#pragma unroll
    for (int rr = 0; rr < 2; ++rr) {
      int r = qrow + rr * 16;
      int s = (r & 2) ^ ((r >> 2) & 1);
      const float* gp = Qg + (size_t)(l0 + lw + r) * DDc + kk * 16;
#pragma unroll
      for (int c = qc0; c < qc0 + 2; ++c) {
        int pc = c ^ s;
        asm volatile("cp.async.cg.shared.global [%0], [%1], 16;\n"
                     :: "r"(sb + (uint32_t)(r * 16 + pc * 4) * 4u),
                        "l"(gp + c * 4));
      }
    }
    asm volatile("cp.async.commit_group;\n" ::: "memory");
  };

  // hoisted Q read word-offsets (lane-constant)
  auto qword = [](int row, int w) {
    int s = (row & 2) ^ ((row >> 2) & 1);
    return row * 16 + ((((w >> 2) ^ s) & 3) << 2) + (w & 3);
  };
  int qo[2][4];
#pragma unroll
  for (int mt = 0; mt < 2; ++mt) {
    qo[mt][0] = qword(mt * 16 + g, t * 2);
    qo[mt][1] = qword(mt * 16 + g + 8, t * 2);
    qo[mt][2] = qword(mt * 16 + g, t * 2 + 8);
    qo[mt][3] = qword(mt * 16 + g + 8, t * 2 + 8);
  }

  float C[2][8][4];
#pragma unroll
  for (int i = 0; i < 2; i++)
#pragma unroll
    for (int j = 0; j < 8; j++)
#pragma unroll
      for (int p = 0; p < 4; p++) C[i][j][p] = 0.0f;

  cpQ(0);
  __syncthreads();   // B stage visible; only block barrier in the kernel

#pragma unroll 1
  for (int kk = 0; kk < 8; ++kk) {
    if (kk < 7) {
      cpQ(kk + 1);
      asm volatile("cp.async.wait_group 1;\n" ::: "memory");
    } else {
      asm volatile("cp.async.wait_group 0;\n" ::: "memory");
    }
    __syncwarp();

    const uint32_t* qb = sm + QOFF + warp * QWBUF + (kk % 3) * 512;
    uint32_t A[2][4];
#pragma unroll
    for (int mt = 0; mt < 2; ++mt) {
#pragma unroll
      for (int j = 0; j < 4; ++j) {
        float2 qv = *reinterpret_cast<const float2*>(qb + qo[mt][j]);
        A[mt][j] = pack_h2(elup(qv.x) * scale, elup(qv.y) * scale);
      }
    }

    int offB = (((kk * 2 + ql) ^ r8) << 4);
#pragma unroll
    for (int np = 0; np < 4; ++np) {
      uint32_t Bh[4], Bl[4];
      ldsm_x4(Bh, bBhi[np] + offB);
      ldsm_x4(Bl, bBlo[np] + offB);
#pragma unroll
      for (int mt = 0; mt < 2; ++mt) {
        mma_f16(C[mt][2 * np], A[mt], Bh);
        mma_f16(C[mt][2 * np], A[mt], Bl);
        mma_f16(C[mt][2 * np + 1], A[mt], Bh + 2);
        mma_f16(C[mt][2 * np + 1], A[mt], Bl + 2);
      }
    }
  }

  // ---- epilogue ----
#pragma unroll
  for (int mt = 0; mt < 2; ++mt)
#pragma unroll
    for (int nt = 0; nt < 8; ++nt) {
      int lr = l0 + lw + mt * 16 + g;
      int e0 = eo + nt * 8 + t * 2;
      *reinterpret_cast<float2*>(Xg + (size_t)lr * DDc + e0) =
          make_float2(C[mt][nt][0], C[mt][nt][1]);
      *reinterpret_cast<float2*>(Xg + (size_t)(lr + 8) * DDc + e0) =
          make_float2(C[mt][nt][2], C[mt][nt][3]);
    }
}

// ---------------------------------------------------------------------------
extern "C" void kernel_launch(void* const* d_in, const int* in_sizes, int n_in,
                              void* d_out, int out_size) {
  const float* Q = (const float*)d_in[0];
  const float* K = (const float*)d_in[1];
  const float* V = (const float*)d_in[2];
  const float* M = (const float*)d_in[3];
  float* X = (float*)d_out;
  (void)in_sizes; (void)n_in; (void)out_size;

  const float scale = powf((float)LLc, -0.25f);

  cudaFuncSetAttribute(ma_pass1, cudaFuncAttributeMaxDynamicSharedMemorySize,
                       (6144 + 3 * 4096) * 4);
  cudaFuncSetAttribute(ma_pass2, cudaFuncAttributeMaxDynamicSharedMemorySize,
                       (QOFF + 8 * QWBUF) * 4);

  ma_init<<<(LLc + 255) / 256, 256>>>(M, scale);
  dim3 g1(CHUNKSc, BHc);
  ma_pass1<<<g1, 256, (6144 + 3 * 4096) * 4>>>(K, V);
  ma_reduce<<<BHc * 64, 128>>>();
  dim3 g2(LLc / 128, BHc);
  ma_pass2<<<g2, 256, (QOFF + 8 * QWBUF) * 4>>>(Q, X, scale);
}

// round 13
// speedup vs baseline: 1.0578x; 1.0578x over previous
#include <cuda_runtime.h>
#include <cuda_fp16.h>
#include <stdint.h>
#include <math.h>

// ---------------------------------------------------------------------------
// MomentumAttention (linear attention), fp16 MMA:
//   Qf = (elu(Q)+1)*scale ; Kf = (elu(K)+1)*mask*scale*mw[l] ; Vf = V*mask
//   KV[d][e] = sum_l Kf[l][d]*Vf[l][e] ;  X = Qf @ KV
// Pass1: K,V single fp16 (1-term). Pass2: Q single, KVT hi/lo (2-term).
// Legacy mma.sync path (tcgen05 unavailable on this build target).
// ---------------------------------------------------------------------------

#define LLc 8192
#define DDc 128
#define BHc 32
#define CHUNKSc 16
#define CLc (LLc / CHUNKSc)   // 512

__device__ float    g_KVp[CHUNKSc * BHc * DDc * DDc];  // per-chunk partials
__device__ float4   g_wm4[2 * LLc / 2];                // {w*m, m, w*m, m} per l-pair
__device__ uint32_t g_KVThi[BHc * DDc * (DDc / 2)];    // [bh][e][d-pair] fp16x2
__device__ uint32_t g_KVTlo[BHc * DDc * (DDc / 2)];

__device__ __forceinline__ float elup(float x) {
  return x > 0.0f ? x + 1.0f : __expf(x);
}

__device__ __forceinline__ uint32_t pack_h2(float a, float b) {
  __half2 h = __floats2half2_rn(a, b);
  return *reinterpret_cast<uint32_t*>(&h);
}

__device__ __forceinline__ void split_pair_h(float a, float b,
                                             uint32_t& hi, uint32_t& lo) {
  __half2 h = __floats2half2_rn(a, b);
  hi = *reinterpret_cast<uint32_t*>(&h);
  float ra = a - __half2float(h.x);
  float rb = b - __half2float(h.y);
  __half2 l2 = __floats2half2_rn(ra, rb);
  lo = *reinterpret_cast<uint32_t*>(&l2);
}

__device__ __forceinline__ void mma_f16(float* c, const uint32_t* a,
                                        const uint32_t* b) {
  asm volatile(
      "mma.sync.aligned.m16n8k16.row.col.f32.f16.f16.f32 "
      "{%0,%1,%2,%3},{%4,%5,%6,%7},{%8,%9},{%0,%1,%2,%3};\n"
      : "+f"(c[0]), "+f"(c[1]), "+f"(c[2]), "+f"(c[3])
      : "r"(a[0]), "r"(a[1]), "r"(a[2]), "r"(a[3]), "r"(b[0]), "r"(b[1]));
}

__device__ __forceinline__ void ldsm_x4(uint32_t* r, uint32_t addr) {
  asm volatile(
      "ldmatrix.sync.aligned.m8n8.x4.shared.b16 {%0,%1,%2,%3}, [%4];"
      : "=r"(r[0]), "=r"(r[1]), "=r"(r[2]), "=r"(r[3])
      : "r"(addr));
}

// ---------------------------------------------------------------------------
__global__ void ma_init(const float* __restrict__ mask, float scale) {
  int idx = blockIdx.x * blockDim.x + threadIdx.x;   // 0 .. 8191
  if (idx < 2 * (LLc / 2)) {
    int b = idx >> 12;
    int l = (idx & 4095) * 2;
    float m0 = mask[b * LLc + l];
    float m1 = mask[b * LLc + l + 1];
    float p0 = powf(0.9f, (float)(LLc - l));
    float p1 = powf(0.9f, (float)(LLc - l - 1));
    float w0 = scale * (1.0f - p0) * 10.0f;
    float w1 = scale * (1.0f - p1) * 10.0f;
    g_wm4[idx] = make_float4(w0 * m0, m0, w1 * m1, m1);
  }
}

// ---------------------------------------------------------------------------
// Pass 1: C[d][e] += sum_l Kf[l][d]*Vf[l][e].  A = Kf fp16, B = Vf fp16
// (single precision term each -> 16 MMAs per 16-l step).
// cp.async raw ring (3 bufs of 16 l) -> transform -> fp16 double buffer.
// smem (words): fp16 bufs: buf b at b*2048 {KH +0, VH +1024};
//               raw ring at 4096 + (s%3)*4096 {rawK +0, rawV +2048}.
// 8 warps, warp tile 32(d) x 64(e).
// ---------------------------------------------------------------------------
__global__ void __launch_bounds__(256, 2)
ma_pass1(const float* __restrict__ Kin, const float* __restrict__ Vin) {
  extern __shared__ uint32_t sm[];
  const int tid = threadIdx.x;
  const int bh = blockIdx.y;
  const int b = bh >> 4;
  const int chunk = blockIdx.x;
  const float* Kg = Kin + (size_t)bh * LLc * DDc;
  const float* Vg = Vin + (size_t)bh * LLc * DDc;
  const float4* Wg = g_wm4 + (size_t)b * (LLc / 2);

  const int warp = tid >> 5, lane = tid & 31;
  const int g = lane >> 2, t = lane & 3;
  const int q = lane >> 3, r8 = lane & 7;
  const int qh = q >> 1, ql = q & 1;
  const int mo = (warp & 3) * 32;    // d
  const int no = (warp >> 2) * 64;   // e

  uint32_t smb = (uint32_t)__cvta_generic_to_shared(sm);

  uint32_t aAddr[2];
#pragma unroll
  for (int mt = 0; mt < 2; ++mt) {
    int row = mo + mt * 16 + ql * 8 + r8;
    aAddr[mt] = smb + (uint32_t)(row * 32) +
                (uint32_t)(((qh ^ ((row >> 2) & 1))) << 4);
  }
  uint32_t bAddr[4];
#pragma unroll
  for (int np = 0; np < 4; ++np) {
    int row = no + np * 16 + qh * 8 + r8;
    bAddr[np] = smb + 4096u + (uint32_t)(row * 32) +
                (uint32_t)(((ql ^ ((row >> 2) & 1))) << 4);
  }

  const int dst = tid & 127;
  const int chk = tid >> 7;
  const int schk = chk ^ ((dst >> 2) & 1);

  float C[2][8][4];
#pragma unroll
  for (int i = 0; i < 2; i++)
#pragma unroll
    for (int j = 0; j < 8; j++)
#pragma unroll
      for (int p = 0; p < 4; p++) C[i][j][p] = 0.0f;

  const int l0c = chunk * CLc;

  const int crow = tid >> 4;
  const int ccol = tid & 15;
  auto cpKV = [&](int s) {
    uint32_t kb = smb + (uint32_t)(4096 + (s % 3) * 4096) * 4u;
    uint32_t vb = kb + 8192u;
    const float* kg = Kg + (size_t)(l0c + s * 16 + crow) * DDc + ccol * 4;
    const float* vg = Vg + (size_t)(l0c + s * 16 + crow) * DDc + ccol * 4;
    uint32_t so = (uint32_t)(crow * 128 + ccol * 4) * 4u;
    asm volatile("cp.async.cg.shared.global [%0], [%1], 16;\n"
                 :: "r"(kb + so), "l"(kg));
    asm volatile("cp.async.cg.shared.global [%0], [%1], 16;\n"
                 :: "r"(kb + so + 256u), "l"(kg + 64));
    asm volatile("cp.async.cg.shared.global [%0], [%1], 16;\n"
                 :: "r"(vb + so), "l"(vg));
    asm volatile("cp.async.cg.shared.global [%0], [%1], 16;\n"
                 :: "r"(vb + so + 256u), "l"(vg + 64));
    asm volatile("cp.async.commit_group;\n" ::: "memory");
  };

  auto transform = [&](int s) {
    const uint32_t* kb = sm + 4096 + (s % 3) * 4096;
    const uint32_t* vb = kb + 2048;
    int l = l0c + s * 16 + chk * 8;
    float4 w4[4];
#pragma unroll
    for (int i = 0; i < 4; ++i) w4[i] = Wg[(l >> 1) + i];
    float kf[8], vf[8];
#pragma unroll
    for (int i = 0; i < 4; ++i) {
      int rw = (chk * 8 + 2 * i) * 128 + dst;
      float k0 = __uint_as_float(kb[rw]);
      float k1 = __uint_as_float(kb[rw + 128]);
      float v0 = __uint_as_float(vb[rw]);
      float v1 = __uint_as_float(vb[rw + 128]);
      kf[2 * i] = elup(k0) * w4[i].x;
      kf[2 * i + 1] = elup(k1) * w4[i].z;
      vf[2 * i] = v0 * w4[i].y;
      vf[2 * i + 1] = v1 * w4[i].w;
    }
    uint4 kh, vh;
    kh.x = pack_h2(kf[0], kf[1]);
    kh.y = pack_h2(kf[2], kf[3]);
    kh.z = pack_h2(kf[4], kf[5]);
    kh.w = pack_h2(kf[6], kf[7]);
    vh.x = pack_h2(vf[0], vf[1]);
    vh.y = pack_h2(vf[2], vf[3]);
    vh.z = pack_h2(vf[4], vf[5]);
    vh.w = pack_h2(vf[6], vf[7]);
    int off = (s & 1) * 2048 + dst * 8 + (schk << 2);
    *reinterpret_cast<uint4*>(sm + off) = kh;
    *reinterpret_cast<uint4*>(sm + off + 1024) = vh;
  };

  auto mmastep = [&](int bsel) {
    const uint32_t bb = (uint32_t)bsel * 8192u;
    uint32_t A[2][4];
#pragma unroll
    for (int mt = 0; mt < 2; ++mt) ldsm_x4(A[mt], aAddr[mt] + bb);
#pragma unroll
    for (int np = 0; np < 4; ++np) {
      uint32_t Bh[4];
      ldsm_x4(Bh, bAddr[np] + bb);
#pragma unroll
      for (int mt = 0; mt < 2; ++mt) {
        mma_f16(C[mt][2 * np], A[mt], Bh);
        mma_f16(C[mt][2 * np + 1], A[mt], Bh + 2);
      }
    }
  };

  cpKV(0);
  cpKV(1);
  cpKV(2);
  asm volatile("cp.async.wait_group 2;\n" ::: "memory");
  __syncthreads();
  transform(0);
  asm volatile("cp.async.wait_group 1;\n" ::: "memory");
  __syncthreads();

#pragma unroll 1
  for (int s = 0; s < 32; ++s) {
    if (s < 29) cpKV(s + 3);
    mmastep(s & 1);
    if (s < 31) transform(s + 1);
    if (s < 29) {
      asm volatile("cp.async.wait_group 1;\n" ::: "memory");
    } else if (s == 29) {
      asm volatile("cp.async.wait_group 0;\n" ::: "memory");
    }
    __syncthreads();
  }

  float* out = g_KVp + (size_t)(chunk * BHc + bh) * DDc * DDc;
#pragma unroll
  for (int mt = 0; mt < 2; ++mt)
#pragma unroll
    for (int nt = 0; nt < 8; ++nt) {
      int d0 = mo + mt * 16 + g;
      int e0 = no + nt * 8 + t * 2;
      *reinterpret_cast<float2*>(out + (size_t)d0 * DDc + e0) =
          make_float2(C[mt][nt][0], C[mt][nt][1]);
      *reinterpret_cast<float2*>(out + (size_t)(d0 + 8) * DDc + e0) =
          make_float2(C[mt][nt][2], C[mt][nt][3]);
    }
}

// ---------------------------------------------------------------------------
__global__ void __launch_bounds__(128) ma_reduce() {
  const int e = threadIdx.x;
  const int bh = blockIdx.x >> 6;
  const int dp = blockIdx.x & 63;
  const int d = dp * 2;
  float a0 = 0.0f, a1 = 0.0f;
  for (int c = 0; c < CHUNKSc; ++c) {
    const float* p = g_KVp + (size_t)(c * BHc + bh) * DDc * DDc;
    a0 += p[(size_t)d * DDc + e];
    a1 += p[(size_t)(d + 1) * DDc + e];
  }
  uint32_t hi, lo;
  split_pair_h(a0, a1, hi, lo);
  g_KVThi[(size_t)bh * 8192 + e * 64 + dp] = hi;
  g_KVTlo[(size_t)bh * 8192 + e * 64 + dp] = lo;
}

// ---------------------------------------------------------------------------
// Pass 2 (R11 version — e-split, warp-private Q ring, 3 CTAs/SM):
// A = Qf single fp16, B = KVT fp16 hi/lo -> 2 MMAs/k16.
// smem words: BHI[0,4096) BLO[4096,8192) Q[8192, 8192+8*768)
// ---------------------------------------------------------------------------
#define QOFF 8192
#define QWBUF 768   // 3 * 256 words per warp

__global__ void __launch_bounds__(256, 3)
ma_pass2(const float* __restrict__ Qin, float* __restrict__ Xout, float scale) {
  extern __shared__ uint32_t sm[];

  const int tid = threadIdx.x;
  const int bh = blockIdx.y >> 1;
  const int eh = blockIdx.y & 1;
  const int l0 = blockIdx.x * 128;
  const float* Qg = Qin + (size_t)bh * LLc * DDc;
  float* Xg = Xout + (size_t)bh * LLc * DDc + eh * 64;

  const int warp = tid >> 5, lane = tid & 31;
  const int g = lane >> 2, t = lane & 3;
  const int q = lane >> 3, r8 = lane & 7;
  const int qh = q >> 1, ql = q & 1;
  const int lw = warp * 16;                 // warp's l offset

  uint32_t smb = (uint32_t)__cvta_generic_to_shared(sm);

  // ---- stage B e-half once (swizzled): 64 rows x 16 uint4 ----
  {
    const uint4* shi = reinterpret_cast<const uint4*>(
        g_KVThi + (size_t)bh * 8192 + (size_t)eh * 4096);
    const uint4* slo = reinterpret_cast<const uint4*>(
        g_KVTlo + (size_t)bh * 8192 + (size_t)eh * 4096);
#pragma unroll
    for (int i = 0; i < 4; ++i) {
      int idx4 = tid + i * 256;        // 0..1023
      int e = idx4 >> 4, c = idx4 & 15;
      int w = e * 64 + ((c ^ (e & 7)) << 2);
      *reinterpret_cast<uint4*>(sm + w) = shi[idx4];
      *reinterpret_cast<uint4*>(sm + 4096 + w) = slo[idx4];
    }
  }

  uint32_t bBhi[4], bBlo[4];
#pragma unroll
  for (int np = 0; np < 4; ++np) {
    int row = np * 16 + qh * 8 + r8;
    bBhi[np] = smb + (uint32_t)(row * 64) * 4u;
    bBlo[np] = smb + (4096u + (uint32_t)(row * 64)) * 4u;
  }

  // ---- per-warp Q ring ----
  const int qrow = lane & 15;           // local row this lane stages
  const int qc0 = (lane >> 4) * 2;      // chunks {0,1} or {2,3}
  const uint32_t qbase = smb + (uint32_t)(QOFF + warp * QWBUF) * 4u;
  const int qsw = (qrow & 2) ^ ((qrow >> 2) & 1);

  auto cpQ = [&](int kk) {
    uint32_t sb = qbase + (uint32_t)((kk % 3) * 256) * 4u;
    const float* gp = Qg + (size_t)(l0 + lw + qrow) * DDc + kk * 16;
#pragma unroll
    for (int c = qc0; c < qc0 + 2; ++c) {
      int pc = c ^ qsw;
      asm volatile("cp.async.cg.shared.global [%0], [%1], 16;\n"
                   :: "r"(sb + (uint32_t)(qrow * 16 + pc * 4) * 4u),
                      "l"(gp + c * 4));
    }
    asm volatile("cp.async.commit_group;\n" ::: "memory");
  };

  auto qword = [](int row, int w) {
    int s = (row & 2) ^ ((row >> 2) & 1);
    return row * 16 + ((((w >> 2) ^ s) & 3) << 2) + (w & 3);
  };

  float C[8][4];
#pragma unroll
  for (int j = 0; j < 8; j++)
#pragma unroll
    for (int p = 0; p < 4; p++) C[j][p] = 0.0f;

  cpQ(0);
  __syncthreads();   // B stage visible; only block barrier in the kernel

#pragma unroll 1
  for (int kk = 0; kk < 8; ++kk) {
    if (kk < 7) {
      cpQ(kk + 1);
      asm volatile("cp.async.wait_group 1;\n" ::: "memory");
    } else {
      asm volatile("cp.async.wait_group 0;\n" ::: "memory");
    }
    __syncwarp();

    const uint32_t* qb = sm + QOFF + warp * QWBUF + (kk % 3) * 256;
    float2 q00 = *reinterpret_cast<const float2*>(qb + qword(g, t * 2));
    float2 q01 = *reinterpret_cast<const float2*>(qb + qword(g, t * 2 + 8));
    float2 q10 = *reinterpret_cast<const float2*>(qb + qword(g + 8, t * 2));
    float2 q11 = *reinterpret_cast<const float2*>(qb + qword(g + 8, t * 2 + 8));

    uint32_t A[4];
    A[0] = pack_h2(elup(q00.x) * scale, elup(q00.y) * scale);
    A[1] = pack_h2(elup(q10.x) * scale, elup(q10.y) * scale);
    A[2] = pack_h2(elup(q01.x) * scale, elup(q01.y) * scale);
    A[3] = pack_h2(elup(q11.x) * scale, elup(q11.y) * scale);

    int offB = (((kk * 2 + ql) ^ r8) << 4);
#pragma unroll
    for (int np = 0; np < 4; ++np) {
      uint32_t Bh[4], Bl[4];
      ldsm_x4(Bh, bBhi[np] + offB);
      ldsm_x4(Bl, bBlo[np] + offB);
      mma_f16(C[2 * np], A, Bh);
      mma_f16(C[2 * np], A, Bl);
      mma_f16(C[2 * np + 1], A, Bh + 2);
      mma_f16(C[2 * np + 1], A, Bl + 2);
    }
  }

  // ---- epilogue ----
#pragma unroll
  for (int nt = 0; nt < 8; ++nt) {
    int lr = l0 + lw + g;
    int e0 = nt * 8 + t * 2;
    *reinterpret_cast<float2*>(Xg + (size_t)lr * DDc + e0) =
        make_float2(C[nt][0], C[nt][1]);
    *reinterpret_cast<float2*>(Xg + (size_t)(lr + 8) * DDc + e0) =
        make_float2(C[nt][2], C[nt][3]);
  }
}

// ---------------------------------------------------------------------------
extern "C" void kernel_launch(void* const* d_in, const int* in_sizes, int n_in,
                              void* d_out, int out_size) {
  const float* Q = (const float*)d_in[0];
  const float* K = (const float*)d_in[1];
  const float* V = (const float*)d_in[2];
  const float* M = (const float*)d_in[3];
  float* X = (float*)d_out;
  (void)in_sizes; (void)n_in; (void)out_size;

  const float scale = powf((float)LLc, -0.25f);

  cudaFuncSetAttribute(ma_pass1, cudaFuncAttributeMaxDynamicSharedMemorySize,
                       (4096 + 3 * 4096) * 4);
  cudaFuncSetAttribute(ma_pass2, cudaFuncAttributeMaxDynamicSharedMemorySize,
                       (QOFF + 8 * QWBUF) * 4);

  ma_init<<<(LLc + 255) / 256, 256>>>(M, scale);
  dim3 g1(CHUNKSc, BHc);
  ma_pass1<<<g1, 256, (4096 + 3 * 4096) * 4>>>(K, V);
  ma_reduce<<<BHc * 64, 128>>>();
  dim3 g2(LLc / 128, BHc * 2);
  ma_pass2<<<g2, 256, (QOFF + 8 * QWBUF) * 4>>>(Q, X, scale);
}

// round 14
// speedup vs baseline: 1.1580x; 1.0947x over previous
#include <cuda_runtime.h>
#include <cuda_fp16.h>
#include <stdint.h>
#include <math.h>

// ---------------------------------------------------------------------------
// MomentumAttention (linear attention), fp16 MMA:
//   Qf = (elu(Q)+1)*scale ; Kf = (elu(K)+1)*mask*scale*mw[l] ; Vf = V*mask
//   KV[d][e] = sum_l Kf[l][d]*Vf[l][e] ;  X = Qf @ KV
// Pass1: K,V single fp16 (1-term). Pass2: Q single, KVT single (1-term).
// Legacy mma.sync path (tcgen05 unavailable on this build target).
// ---------------------------------------------------------------------------

#define LLc 8192
#define DDc 128
#define BHc 32
#define CHUNKSc 16
#define CLc (LLc / CHUNKSc)   // 512

__device__ float    g_KVp[CHUNKSc * BHc * DDc * DDc];  // per-chunk partials
__device__ float4   g_wm4[2 * LLc / 2];                // {w*m, m, w*m, m} per l-pair
__device__ uint32_t g_KVThi[BHc * DDc * (DDc / 2)];    // [bh][e][d-pair] fp16x2

__device__ __forceinline__ float elup(float x) {
  return x > 0.0f ? x + 1.0f : __expf(x);
}

__device__ __forceinline__ uint32_t pack_h2(float a, float b) {
  __half2 h = __floats2half2_rn(a, b);
  return *reinterpret_cast<uint32_t*>(&h);
}

__device__ __forceinline__ void mma_f16(float* c, const uint32_t* a,
                                        const uint32_t* b) {
  asm volatile(
      "mma.sync.aligned.m16n8k16.row.col.f32.f16.f16.f32 "
      "{%0,%1,%2,%3},{%4,%5,%6,%7},{%8,%9},{%0,%1,%2,%3};\n"
      : "+f"(c[0]), "+f"(c[1]), "+f"(c[2]), "+f"(c[3])
      : "r"(a[0]), "r"(a[1]), "r"(a[2]), "r"(a[3]), "r"(b[0]), "r"(b[1]));
}

__device__ __forceinline__ void ldsm_x4(uint32_t* r, uint32_t addr) {
  asm volatile(
      "ldmatrix.sync.aligned.m8n8.x4.shared.b16 {%0,%1,%2,%3}, [%4];"
      : "=r"(r[0]), "=r"(r[1]), "=r"(r[2]), "=r"(r[3])
      : "r"(addr));
}

// ---------------------------------------------------------------------------
__global__ void ma_init(const float* __restrict__ mask, float scale) {
  int idx = blockIdx.x * blockDim.x + threadIdx.x;   // 0 .. 8191
  if (idx < 2 * (LLc / 2)) {
    int b = idx >> 12;
    int l = (idx & 4095) * 2;
    float m0 = mask[b * LLc + l];
    float m1 = mask[b * LLc + l + 1];
    float p0 = powf(0.9f, (float)(LLc - l));
    float p1 = powf(0.9f, (float)(LLc - l - 1));
    float w0 = scale * (1.0f - p0) * 10.0f;
    float w1 = scale * (1.0f - p1) * 10.0f;
    g_wm4[idx] = make_float4(w0 * m0, m0, w1 * m1, m1);
  }
}

// ---------------------------------------------------------------------------
// Pass 1 (unchanged from R13): A = Kf fp16, B = Vf fp16, 16 MMAs / 16-l step.
// ---------------------------------------------------------------------------
__global__ void __launch_bounds__(256, 2)
ma_pass1(const float* __restrict__ Kin, const float* __restrict__ Vin) {
  extern __shared__ uint32_t sm[];
  const int tid = threadIdx.x;
  const int bh = blockIdx.y;
  const int b = bh >> 4;
  const int chunk = blockIdx.x;
  const float* Kg = Kin + (size_t)bh * LLc * DDc;
  const float* Vg = Vin + (size_t)bh * LLc * DDc;
  const float4* Wg = g_wm4 + (size_t)b * (LLc / 2);

  const int warp = tid >> 5, lane = tid & 31;
  const int g = lane >> 2, t = lane & 3;
  const int q = lane >> 3, r8 = lane & 7;
  const int qh = q >> 1, ql = q & 1;
  const int mo = (warp & 3) * 32;    // d
  const int no = (warp >> 2) * 64;   // e

  uint32_t smb = (uint32_t)__cvta_generic_to_shared(sm);

  uint32_t aAddr[2];
#pragma unroll
  for (int mt = 0; mt < 2; ++mt) {
    int row = mo + mt * 16 + ql * 8 + r8;
    aAddr[mt] = smb + (uint32_t)(row * 32) +
                (uint32_t)(((qh ^ ((row >> 2) & 1))) << 4);
  }
  uint32_t bAddr[4];
#pragma unroll
  for (int np = 0; np < 4; ++np) {
    int row = no + np * 16 + qh * 8 + r8;
    bAddr[np] = smb + 4096u + (uint32_t)(row * 32) +
                (uint32_t)(((ql ^ ((row >> 2) & 1))) << 4);
  }

  const int dst = tid & 127;
  const int chk = tid >> 7;
  const int schk = chk ^ ((dst >> 2) & 1);

  float C[2][8][4];
#pragma unroll
  for (int i = 0; i < 2; i++)
#pragma unroll
    for (int j = 0; j < 8; j++)
#pragma unroll
      for (int p = 0; p < 4; p++) C[i][j][p] = 0.0f;

  const int l0c = chunk * CLc;

  const int crow = tid >> 4;
  const int ccol = tid & 15;
  auto cpKV = [&](int s) {
    uint32_t kb = smb + (uint32_t)(4096 + (s % 3) * 4096) * 4u;
    uint32_t vb = kb + 8192u;
    const float* kg = Kg + (size_t)(l0c + s * 16 + crow) * DDc + ccol * 4;
    const float* vg = Vg + (size_t)(l0c + s * 16 + crow) * DDc + ccol * 4;
    uint32_t so = (uint32_t)(crow * 128 + ccol * 4) * 4u;
    asm volatile("cp.async.cg.shared.global [%0], [%1], 16;\n"
                 :: "r"(kb + so), "l"(kg));
    asm volatile("cp.async.cg.shared.global [%0], [%1], 16;\n"
                 :: "r"(kb + so + 256u), "l"(kg + 64));
    asm volatile("cp.async.cg.shared.global [%0], [%1], 16;\n"
                 :: "r"(vb + so), "l"(vg));
    asm volatile("cp.async.cg.shared.global [%0], [%1], 16;\n"
                 :: "r"(vb + so + 256u), "l"(vg + 64));
    asm volatile("cp.async.commit_group;\n" ::: "memory");
  };

  auto transform = [&](int s) {
    const uint32_t* kb = sm + 4096 + (s % 3) * 4096;
    const uint32_t* vb = kb + 2048;
    int l = l0c + s * 16 + chk * 8;
    float4 w4[4];
#pragma unroll
    for (int i = 0; i < 4; ++i) w4[i] = Wg[(l >> 1) + i];
    float kf[8], vf[8];
#pragma unroll
    for (int i = 0; i < 4; ++i) {
      int rw = (chk * 8 + 2 * i) * 128 + dst;
      float k0 = __uint_as_float(kb[rw]);
      float k1 = __uint_as_float(kb[rw + 128]);
      float v0 = __uint_as_float(vb[rw]);
      float v1 = __uint_as_float(vb[rw + 128]);
      kf[2 * i] = elup(k0) * w4[i].x;
      kf[2 * i + 1] = elup(k1) * w4[i].z;
      vf[2 * i] = v0 * w4[i].y;
      vf[2 * i + 1] = v1 * w4[i].w;
    }
    uint4 kh, vh;
    kh.x = pack_h2(kf[0], kf[1]);
    kh.y = pack_h2(kf[2], kf[3]);
    kh.z = pack_h2(kf[4], kf[5]);
    kh.w = pack_h2(kf[6], kf[7]);
    vh.x = pack_h2(vf[0], vf[1]);
    vh.y = pack_h2(vf[2], vf[3]);
    vh.z = pack_h2(vf[4], vf[5]);
    vh.w = pack_h2(vf[6], vf[7]);
    int off = (s & 1) * 2048 + dst * 8 + (schk << 2);
    *reinterpret_cast<uint4*>(sm + off) = kh;
    *reinterpret_cast<uint4*>(sm + off + 1024) = vh;
  };

  auto mmastep = [&](int bsel) {
    const uint32_t bb = (uint32_t)bsel * 8192u;
    uint32_t A[2][4];
#pragma unroll
    for (int mt = 0; mt < 2; ++mt) ldsm_x4(A[mt], aAddr[mt] + bb);
#pragma unroll
    for (int np = 0; np < 4; ++np) {
      uint32_t Bh[4];
      ldsm_x4(Bh, bAddr[np] + bb);
#pragma unroll
      for (int mt = 0; mt < 2; ++mt) {
        mma_f16(C[mt][2 * np], A[mt], Bh);
        mma_f16(C[mt][2 * np + 1], A[mt], Bh + 2);
      }
    }
  };

  cpKV(0);
  cpKV(1);
  cpKV(2);
  asm volatile("cp.async.wait_group 2;\n" ::: "memory");
  __syncthreads();
  transform(0);
  asm volatile("cp.async.wait_group 1;\n" ::: "memory");
  __syncthreads();

#pragma unroll 1
  for (int s = 0; s < 32; ++s) {
    if (s < 29) cpKV(s + 3);
    mmastep(s & 1);
    if (s < 31) transform(s + 1);
    if (s < 29) {
      asm volatile("cp.async.wait_group 1;\n" ::: "memory");
    } else if (s == 29) {
      asm volatile("cp.async.wait_group 0;\n" ::: "memory");
    }
    __syncthreads();
  }

  float* out = g_KVp + (size_t)(chunk * BHc + bh) * DDc * DDc;
#pragma unroll
  for (int mt = 0; mt < 2; ++mt)
#pragma unroll
    for (int nt = 0; nt < 8; ++nt) {
      int d0 = mo + mt * 16 + g;
      int e0 = no + nt * 8 + t * 2;
      *reinterpret_cast<float2*>(out + (size_t)d0 * DDc + e0) =
          make_float2(C[mt][nt][0], C[mt][nt][1]);
      *reinterpret_cast<float2*>(out + (size_t)(d0 + 8) * DDc + e0) =
          make_float2(C[mt][nt][2], C[mt][nt][3]);
    }
}

// ---------------------------------------------------------------------------
__global__ void __launch_bounds__(128) ma_reduce() {
  const int e = threadIdx.x;
  const int bh = blockIdx.x >> 6;
  const int dp = blockIdx.x & 63;
  const int d = dp * 2;
  float a0 = 0.0f, a1 = 0.0f;
  for (int c = 0; c < CHUNKSc; ++c) {
    const float* p = g_KVp + (size_t)(c * BHc + bh) * DDc * DDc;
    a0 += p[(size_t)d * DDc + e];
    a1 += p[(size_t)(d + 1) * DDc + e];
  }
  g_KVThi[(size_t)bh * 8192 + e * 64 + dp] = pack_h2(a0, a1);
}

// ---------------------------------------------------------------------------
// Pass 2 (e-split, warp-private Q ring, B single fp16 -> 1-term MMA):
// CTA = (128 l) x (bh, e-half of 64). B e-half smem-resident (16 KB).
// Q per-warp cp.async ring, no block barriers in the main loop.
// smem words: B[0,4096) Q[4096, 4096+8*768)
// ---------------------------------------------------------------------------
#define QOFF 4096
#define QWBUF 768   // 3 * 256 words per warp

__global__ void __launch_bounds__(256, 3)
ma_pass2(const float* __restrict__ Qin, float* __restrict__ Xout, float scale) {
  extern __shared__ uint32_t sm[];

  const int tid = threadIdx.x;
  const int bh = blockIdx.y >> 1;
  const int eh = blockIdx.y & 1;
  const int l0 = blockIdx.x * 128;
  const float* Qg = Qin + (size_t)bh * LLc * DDc;
  float* Xg = Xout + (size_t)bh * LLc * DDc + eh * 64;

  const int warp = tid >> 5, lane = tid & 31;
  const int g = lane >> 2, t = lane & 3;
  const int q = lane >> 3, r8 = lane & 7;
  const int qh = q >> 1, ql = q & 1;
  const int lw = warp * 16;                 // warp's l offset

  uint32_t smb = (uint32_t)__cvta_generic_to_shared(sm);

  // ---- stage B e-half once (swizzled): 64 rows x 16 uint4 ----
  {
    const uint4* shi = reinterpret_cast<const uint4*>(
        g_KVThi + (size_t)bh * 8192 + (size_t)eh * 4096);
#pragma unroll
    for (int i = 0; i < 4; ++i) {
      int idx4 = tid + i * 256;        // 0..1023
      int e = idx4 >> 4, c = idx4 & 15;
      int w = e * 64 + ((c ^ (e & 7)) << 2);
      *reinterpret_cast<uint4*>(sm + w) = shi[idx4];
    }
  }

  uint32_t bBhi[4];
#pragma unroll
  for (int np = 0; np < 4; ++np) {
    int row = np * 16 + qh * 8 + r8;
    bBhi[np] = smb + (uint32_t)(row * 64) * 4u;
  }

  // ---- per-warp Q ring ----
  const int qrow = lane & 15;           // local row this lane stages
  const int qc0 = (lane >> 4) * 2;      // chunks {0,1} or {2,3}
  const uint32_t qbase = smb + (uint32_t)(QOFF + warp * QWBUF) * 4u;
  const int qsw = (qrow & 2) ^ ((qrow >> 2) & 1);

  auto cpQ = [&](int kk) {
    uint32_t sb = qbase + (uint32_t)((kk % 3) * 256) * 4u;
    const float* gp = Qg + (size_t)(l0 + lw + qrow) * DDc + kk * 16;
#pragma unroll
    for (int c = qc0; c < qc0 + 2; ++c) {
      int pc = c ^ qsw;
      asm volatile("cp.async.cg.shared.global [%0], [%1], 16;\n"
                   :: "r"(sb + (uint32_t)(qrow * 16 + pc * 4) * 4u),
                      "l"(gp + c * 4));
    }
    asm volatile("cp.async.commit_group;\n" ::: "memory");
  };

  auto qword = [](int row, int w) {
    int s = (row & 2) ^ ((row >> 2) & 1);
    return row * 16 + ((((w >> 2) ^ s) & 3) << 2) + (w & 3);
  };

  float C[8][4];
#pragma unroll
  for (int j = 0; j < 8; j++)
#pragma unroll
    for (int p = 0; p < 4; p++) C[j][p] = 0.0f;

  cpQ(0);
  __syncthreads();   // B stage visible; only block barrier in the kernel

#pragma unroll 1
  for (int kk = 0; kk < 8; ++kk) {
    if (kk < 7) {
      cpQ(kk + 1);
      asm volatile("cp.async.wait_group 1;\n" ::: "memory");
    } else {
      asm volatile("cp.async.wait_group 0;\n" ::: "memory");
    }
    __syncwarp();

    const uint32_t* qb = sm + QOFF + warp * QWBUF + (kk % 3) * 256;
    float2 q00 = *reinterpret_cast<const float2*>(qb + qword(g, t * 2));
    float2 q01 = *reinterpret_cast<const float2*>(qb + qword(g, t * 2 + 8));
    float2 q10 = *reinterpret_cast<const float2*>(qb + qword(g + 8, t * 2));
    float2 q11 = *reinterpret_cast<const float2*>(qb + qword(g + 8, t * 2 + 8));

    uint32_t A[4];
    A[0] = pack_h2(elup(q00.x) * scale, elup(q00.y) * scale);
    A[1] = pack_h2(elup(q10.x) * scale, elup(q10.y) * scale);
    A[2] = pack_h2(elup(q01.x) * scale, elup(q01.y) * scale);
    A[3] = pack_h2(elup(q11.x) * scale, elup(q11.y) * scale);

    int offB = (((kk * 2 + ql) ^ r8) << 4);
#pragma unroll
    for (int np = 0; np < 4; ++np) {
      uint32_t Bh[4];
      ldsm_x4(Bh, bBhi[np] + offB);
      mma_f16(C[2 * np], A, Bh);
      mma_f16(C[2 * np + 1], A, Bh + 2);
    }
  }

  // ---- epilogue ----
#pragma unroll
  for (int nt = 0; nt < 8; ++nt) {
    int lr = l0 + lw + g;
    int e0 = nt * 8 + t * 2;
    *reinterpret_cast<float2*>(Xg + (size_t)lr * DDc + e0) =
        make_float2(C[nt][0], C[nt][1]);
    *reinterpret_cast<float2*>(Xg + (size_t)(lr + 8) * DDc + e0) =
        make_float2(C[nt][2], C[nt][3]);
  }
}

// ---------------------------------------------------------------------------
extern "C" void kernel_launch(void* const* d_in, const int* in_sizes, int n_in,
                              void* d_out, int out_size) {
  const float* Q = (const float*)d_in[0];
  const float* K = (const float*)d_in[1];
  const float* V = (const float*)d_in[2];
  const float* M = (const float*)d_in[3];
  float* X = (float*)d_out;
  (void)in_sizes; (void)n_in; (void)out_size;

  const float scale = powf((float)LLc, -0.25f);

  cudaFuncSetAttribute(ma_pass1, cudaFuncAttributeMaxDynamicSharedMemorySize,
                       (4096 + 3 * 4096) * 4);
  cudaFuncSetAttribute(ma_pass2, cudaFuncAttributeMaxDynamicSharedMemorySize,
                       (QOFF + 8 * QWBUF) * 4);

  ma_init<<<(LLc + 255) / 256, 256>>>(M, scale);
  dim3 g1(CHUNKSc, BHc);
  ma_pass1<<<g1, 256, (4096 + 3 * 4096) * 4>>>(K, V);
  ma_reduce<<<BHc * 64, 128>>>();
  dim3 g2(LLc / 128, BHc * 2);
  ma_pass2<<<g2, 256, (QOFF + 8 * QWBUF) * 4>>>(Q, X, scale);
}